// round 13
// baseline (speedup 1.0000x reference)
#include <cuda_runtime.h>
#include <cuda_fp16.h>
#include <math.h>
#include <stdint.h>

#define Bn 8
#define Cc 128
#define Aa 16
#define Nn 4096

// log2(e) * (1/sqrt(16)) folded into Q so P = exp2(S)
#define QSCALE 0.3606737602222409f

// Scratch (no allocations allowed)
__device__ __align__(16) __half g_Qh[Bn * Nn * Aa];   // [b][n][16], prescaled
__device__ __align__(16) __half g_Kh[Bn * Nn * Aa];   // [b][n][16]
__device__ __align__(16) __half g_Vh[Bn * Cc * Nn];   // [b][c][n] channel-major

__device__ __forceinline__ uint32_t smem_u32(const void* p) {
    uint32_t a;
    asm("{ .reg .u64 t; cvta.to.shared.u64 t, %1; cvt.u32.u64 %0, t; }"
        : "=r"(a) : "l"(p));
    return a;
}
__device__ __forceinline__ float ex2f(float x) {
    float y; asm("ex2.approx.ftz.f32 %0, %1;" : "=f"(y) : "f"(x)); return y;
}
__device__ __forceinline__ uint32_t packh2(float hi, float lo) {
    uint32_t r;
    asm("cvt.rn.f16x2.f32 %0, %1, %2;" : "=r"(r) : "f"(hi), "f"(lo));
    return r;
}
__device__ __forceinline__ void cp16(uint32_t dst, const void* src) {
    asm volatile("cp.async.cg.shared.global [%0], [%1], 16;"
                 :: "r"(dst), "l"(src) : "memory");
}
#define CP_COMMIT() asm volatile("cp.async.commit_group;" ::: "memory")
#define CP_WAIT_ALL() asm volatile("cp.async.wait_group 0;" ::: "memory")

#define LDSM4(r, addr)                                                        \
    asm volatile("ldmatrix.sync.aligned.m8n8.x4.shared.b16 {%0,%1,%2,%3}, [%4];" \
                 : "=r"((r)[0]), "=r"((r)[1]), "=r"((r)[2]), "=r"((r)[3])     \
                 : "r"(addr))

__device__ __forceinline__ void mma_f16(float* d, const uint32_t* a,
                                        uint32_t b0, uint32_t b1) {
    asm volatile(
        "mma.sync.aligned.m16n8k16.row.col.f32.f16.f16.f32 "
        "{%0,%1,%2,%3}, {%4,%5,%6,%7}, {%8,%9}, {%0,%1,%2,%3};"
        : "+f"(d[0]), "+f"(d[1]), "+f"(d[2]), "+f"(d[3])
        : "r"(a[0]), "r"(a[1]), "r"(a[2]), "r"(a[3]), "r"(b0), "r"(b1));
}

// ---------------------------------------------------------------------------
// Q/K projection -> fp16 [b][n][16]; Q pre-scaled by 0.25*log2(e)
// C-split x2: 256 threads = 128 px * 2 halves; partials combined in smem.
// ---------------------------------------------------------------------------
__global__ __launch_bounds__(256) void proj_qk_kernel(
    const float* __restrict__ x,
    const float* __restrict__ Wq, const float* __restrict__ bq,
    const float* __restrict__ Wk, const float* __restrict__ bk)
{
    __shared__ float Wqs[Aa * Cc];
    __shared__ float Wks[Aa * Cc];
    __shared__ float U[4224];          // union: Xs[2][16][128] / Part[128][33]

    int b   = blockIdx.y;
    int n0  = blockIdx.x * 128;
    int tid = threadIdx.x;
    int h   = tid >> 7;                // c-half: 0 -> c 0..63, 1 -> c 64..127
    int px  = tid & 127;

    for (int i = tid; i < Aa * Cc; i += 256) { Wqs[i] = Wq[i]; Wks[i] = Wk[i]; }

    float qa[Aa], ka[Aa];
#pragma unroll
    for (int a = 0; a < Aa; a++) { qa[a] = 0.f; ka[a] = 0.f; }

    const float* xb = x + (size_t)b * Cc * Nn + n0;
    float* Xs = U;                     // [2][16][128]

    for (int t = 0; t < 4; t++) {
        int cg = h * 64 + t * 16;
        __syncthreads();
#pragma unroll
        for (int cc = 0; cc < 16; cc++)
            Xs[h * 2048 + cc * 128 + px] = xb[(size_t)(cg + cc) * Nn + px];
        __syncthreads();
#pragma unroll 4
        for (int cc = 0; cc < 16; cc++) {
            float xv = Xs[h * 2048 + cc * 128 + px];
            int c = cg + cc;
#pragma unroll
            for (int a = 0; a < Aa; a++) {
                qa[a] += Wqs[a * Cc + c] * xv;
                ka[a] += Wks[a * Cc + c] * xv;
            }
        }
    }

    __syncthreads();                   // Xs reads done; reuse U as Part
    float* Part = U;                   // [128][33]
    if (h == 1) {
#pragma unroll
        for (int a = 0; a < Aa; a++) {
            Part[px * 33 + a]      = qa[a];
            Part[px * 33 + 16 + a] = ka[a];
        }
    }
    __syncthreads();
    if (h == 0) {
#pragma unroll
        for (int a = 0; a < Aa; a++) {
            qa[a] += Part[px * 33 + a];
            ka[a] += Part[px * 33 + 16 + a];
        }
        int n = n0 + px;
        __half2* qo = (__half2*)(g_Qh + ((size_t)b * Nn + n) * Aa);
        __half2* ko = (__half2*)(g_Kh + ((size_t)b * Nn + n) * Aa);
#pragma unroll
        for (int a2 = 0; a2 < 8; a2++) {
            float q0v = (qa[2 * a2]     + bq[2 * a2])     * QSCALE;
            float q1v = (qa[2 * a2 + 1] + bq[2 * a2 + 1]) * QSCALE;
            qo[a2] = __floats2half2_rn(q0v, q1v);
            ko[a2] = __floats2half2_rn(ka[2 * a2] + bk[2 * a2],
                                       ka[2 * a2 + 1] + bk[2 * a2 + 1]);
        }
    }
}

// ---------------------------------------------------------------------------
// V projection -> fp16 [b][c][n] (channel-major). Tile 32c x 256n, 128 thr.
// (R4 proven)
// ---------------------------------------------------------------------------
__global__ __launch_bounds__(128) void proj_v_kernel(
    const float* __restrict__ x,
    const float* __restrict__ Wv, const float* __restrict__ bv)
{
    __shared__ float Wvs[32][33];
    __shared__ float Xs[32][256];

    int b    = blockIdx.z;
    int c0   = blockIdx.y * 32;
    int n0   = blockIdx.x * 256;
    int tid  = threadIdx.x;
    int lane = tid & 31;
    int wg   = tid >> 5;

    float acc[8][8];
#pragma unroll
    for (int ci = 0; ci < 8; ci++)
#pragma unroll
        for (int j = 0; j < 8; j++) acc[ci][j] = 0.f;

    for (int k0 = 0; k0 < Cc; k0 += 32) {
        __syncthreads();
#pragma unroll
        for (int i = 0; i < 8; i++) {
            int idx = tid + i * 128;
            int kk = idx >> 5, cc = idx & 31;
            Wvs[kk][cc] = Wv[(size_t)(c0 + cc) * Cc + k0 + kk];
        }
#pragma unroll
        for (int i = 0; i < 64; i++) {
            int idx = tid + i * 128;
            int kk = idx >> 8, nn = idx & 255;
            Xs[kk][nn] = x[((size_t)b * Cc + k0 + kk) * Nn + n0 + nn];
        }
        __syncthreads();
#pragma unroll 4
        for (int kk = 0; kk < 32; kk++) {
            float xv[8];
#pragma unroll
            for (int j = 0; j < 8; j++) xv[j] = Xs[kk][lane + j * 32];
#pragma unroll
            for (int ci = 0; ci < 8; ci++) {
                float w = Wvs[kk][wg * 8 + ci];
#pragma unroll
                for (int j = 0; j < 8; j++) acc[ci][j] += w * xv[j];
            }
        }
    }

#pragma unroll
    for (int ci = 0; ci < 8; ci++) {
        int c = c0 + wg * 8 + ci;
        float bias = bv[c];
        __half* vo = g_Vh + ((size_t)b * Cc + c) * Nn + n0;
#pragma unroll
        for (int j = 0; j < 8; j++)
            vo[lane + j * 32] = __float2half_rn(acc[ci][j] + bias);
    }
}

// ---------------------------------------------------------------------------
// Flash attention via mma.sync, 2-D warp tiling.
// CTA: 64 queries, 4 warps (iq = wid>>1 -> 32q, jc = wid&1 -> 64ch each).
// V fragments feed 2 m-tiles (half the LDSM/MMA of the 1-D tiling).
// grid (64, 8) = 512 CTAs, 128 threads, 3 CTAs/SM.
// ---------------------------------------------------------------------------
#define KT 64
#define NITER (Nn / KT)
#define K_BYTES (64 * 48)               // 3072
#define V_BYTES (128 * 144)             // 18432
#define BUF_BYTES (K_BYTES + V_BYTES)   // 21504
#define ATTN_SMEM (2 * BUF_BYTES)       // 43008 (>= 64*133*4 stage)

__global__ __launch_bounds__(128, 3) void attn_kernel(float* __restrict__ out)
{
    extern __shared__ char smem[];
    const uint32_t sb = smem_u32(smem);
    const int tid  = threadIdx.x;
    const int wid  = tid >> 5;
    const int lane = tid & 31;
    const int lr   = lane & 7, lg = lane >> 3;   // ldmatrix row / group
    const int iq   = wid >> 1;                   // q-half (32 queries)
    const int jc   = wid & 1;                    // channel-half (64 ch)
    const int b    = blockIdx.y;
    const int q0g  = blockIdx.x * 64;

    const __half* Kg = g_Kh + (size_t)b * Nn * Aa;
    const __half* Vg = g_Vh + (size_t)b * Cc * Nn;

    // Q fragments for 2 m-tiles (rows iq*32 + mt*16 + ...)
    const int qrow = lane >> 2, qcb = (lane & 3) * 4;
    uint32_t qa[2][4];
#pragma unroll
    for (int mt = 0; mt < 2; mt++) {
        const char* qp = (const char*)(g_Qh
            + ((size_t)b * Nn + q0g + iq * 32 + mt * 16) * Aa);
        qa[mt][0] = *(const uint32_t*)(qp + qrow * 32 + qcb);
        qa[mt][1] = *(const uint32_t*)(qp + (qrow + 8) * 32 + qcb);
        qa[mt][2] = *(const uint32_t*)(qp + qrow * 32 + qcb + 16);
        qa[mt][3] = *(const uint32_t*)(qp + (qrow + 8) * 32 + qcb + 16);
    }

    float o[2][8][4];
#pragma unroll
    for (int mt = 0; mt < 2; mt++)
#pragma unroll
        for (int t = 0; t < 8; t++)
#pragma unroll
            for (int j = 0; j < 4; j++) o[mt][t][j] = 0.f;
    float l0[2] = {0.f, 0.f}, l1[2] = {0.f, 0.f};

    auto fill = [&](int kt, int buf) {
        uint32_t kb = sb + buf * BUF_BYTES;
        uint32_t vb = kb + K_BYTES;
        {   // K: 64 keys x 2 16B chunks = 128 cp
            int key = tid >> 1, h = tid & 1;
            cp16(kb + key * 48 + h * 16,
                 (const char*)Kg + ((size_t)(kt * KT + key) * Aa + h * 8) * 2);
        }
#pragma unroll
        for (int i = 0; i < 8; i++) {   // V: 128ch x 8 16B segs = 1024 cp
            int idx = tid + i * 128;
            int c = idx >> 3, seg = idx & 7;
            cp16(vb + c * 144 + seg * 16,
                 (const char*)Vg + ((size_t)c * Nn + kt * KT + seg * 8) * 2);
        }
        CP_COMMIT();
    };

    fill(0, 0);

    for (int kt = 0; kt < NITER; kt++) {
        CP_WAIT_ALL();
        __syncthreads();
        if (kt + 1 < NITER) fill(kt + 1, (kt + 1) & 1);

        uint32_t kb = sb + (kt & 1) * BUF_BYTES;
        uint32_t vb = kb + K_BYTES;

        // K fragments for all 64 keys, loaded once, reused by both m-tiles
        uint32_t kf[4][4];
#pragma unroll
        for (int nt2 = 0; nt2 < 4; nt2++) {
            uint32_t addr = kb + (uint32_t)(nt2 * 16 + lr + (lg & 2) * 4) * 48
                               + (uint32_t)(lg & 1) * 16;
            LDSM4(kf[nt2], addr);
        }

        // S = Q K^T per m-tile; P = exp2(S) packed to fp16 A fragments
        uint32_t amt[2][4][4];
#pragma unroll
        for (int mt = 0; mt < 2; mt++) {
            float s[8][4];
#pragma unroll
            for (int i = 0; i < 8; i++)
#pragma unroll
                for (int j = 0; j < 4; j++) s[i][j] = 0.f;
#pragma unroll
            for (int nt2 = 0; nt2 < 4; nt2++) {
                mma_f16(s[2 * nt2],     qa[mt], kf[nt2][0], kf[nt2][1]);
                mma_f16(s[2 * nt2 + 1], qa[mt], kf[nt2][2], kf[nt2][3]);
            }
#pragma unroll
            for (int i = 0; i < 8; i++) {
                s[i][0] = ex2f(s[i][0]);
                s[i][1] = ex2f(s[i][1]);
                s[i][2] = ex2f(s[i][2]);
                s[i][3] = ex2f(s[i][3]);
                l0[mt] += s[i][0] + s[i][1];
                l1[mt] += s[i][2] + s[i][3];
            }
#pragma unroll
            for (int ks = 0; ks < 4; ks++) {
                amt[mt][ks][0] = packh2(s[2 * ks][1],     s[2 * ks][0]);
                amt[mt][ks][1] = packh2(s[2 * ks][3],     s[2 * ks][2]);
                amt[mt][ks][2] = packh2(s[2 * ks + 1][1], s[2 * ks + 1][0]);
                amt[mt][ks][3] = packh2(s[2 * ks + 1][3], s[2 * ks + 1][3]);
                amt[mt][ks][3] = packh2(s[2 * ks + 1][3], s[2 * ks + 1][2]);
            }
        }

        // O += P V : warp's 64 channels, V fragment reused by both m-tiles
#pragma unroll
        for (int ks = 0; ks < 4; ks++) {
#pragma unroll
            for (int t2 = 0; t2 < 4; t2++) {
                int t2g = jc * 4 + t2;
                uint32_t bv[4];
                uint32_t addr = vb + (uint32_t)(t2g * 16 + lr + (lg & 2) * 4) * 144
                                   + (uint32_t)(ks * 32) + (uint32_t)(lg & 1) * 16;
                LDSM4(bv, addr);
                mma_f16(o[0][2 * t2],     amt[0][ks], bv[0], bv[1]);
                mma_f16(o[0][2 * t2 + 1], amt[0][ks], bv[2], bv[3]);
                mma_f16(o[1][2 * t2],     amt[1][ks], bv[0], bv[1]);
                mma_f16(o[1][2 * t2 + 1], amt[1][ks], bv[2], bv[3]);
            }
        }
    }

    // row sums (lanes sharing a row differ in bits 0..1)
    float inv0[2], inv1[2];
#pragma unroll
    for (int mt = 0; mt < 2; mt++) {
        l0[mt] += __shfl_xor_sync(0xffffffffu, l0[mt], 1);
        l0[mt] += __shfl_xor_sync(0xffffffffu, l0[mt], 2);
        l1[mt] += __shfl_xor_sync(0xffffffffu, l1[mt], 1);
        l1[mt] += __shfl_xor_sync(0xffffffffu, l1[mt], 2);
        inv0[mt] = 1.f / l0[mt];
        inv1[mt] = 1.f / l1[mt];
    }

    __syncthreads();   // done with tile buffers; reuse smem as stage [64][133]
    float* stage = (float*)smem;
    const int cb = (lane & 3) * 2;
#pragma unroll
    for (int mt = 0; mt < 2; mt++) {
        int r0 = iq * 32 + mt * 16 + qrow;
#pragma unroll
        for (int t = 0; t < 8; t++) {
            int ch = jc * 64 + t * 8 + cb;
            stage[r0 * 133 + ch]           = o[mt][t][0] * inv0[mt];
            stage[r0 * 133 + ch + 1]       = o[mt][t][1] * inv0[mt];
            stage[(r0 + 8) * 133 + ch]     = o[mt][t][2] * inv1[mt];
            stage[(r0 + 8) * 133 + ch + 1] = o[mt][t][3] * inv1[mt];
        }
    }
    __syncthreads();

    // coalesced write: 64 n x 128 ch
    const int nn = tid & 63, hi = tid >> 6;
#pragma unroll 8
    for (int it = 0; it < 64; it++) {
        int ch = it * 2 + hi;
        out[((size_t)b * Cc + ch) * Nn + q0g + nn] = stage[nn * 133 + ch];
    }
}

// ---------------------------------------------------------------------------
extern "C" void kernel_launch(void* const* d_in, const int* in_sizes, int n_in,
                              void* d_out, int out_size)
{
    const float* x  = (const float*)d_in[0];
    const float* Wq = (const float*)d_in[1];
    const float* bq = (const float*)d_in[2];
    const float* Wk = (const float*)d_in[3];
    const float* bk = (const float*)d_in[4];
    const float* Wv = (const float*)d_in[5];
    const float* bv = (const float*)d_in[6];
    float* out = (float*)d_out;

    proj_qk_kernel<<<dim3(Nn / 128, Bn), 256>>>(x, Wq, bq, Wk, bk);
    proj_v_kernel<<<dim3(Nn / 256, Cc / 32, Bn), 128>>>(x, Wv, bv);

    cudaFuncSetAttribute(attn_kernel,
                         cudaFuncAttributeMaxDynamicSharedMemorySize,
                         ATTN_SMEM);
    attn_kernel<<<dim3(Nn / 64, Bn), 128, ATTN_SMEM>>>(out);
}

// round 14
// speedup vs baseline: 1.1970x; 1.1970x over previous
#include <cuda_runtime.h>
#include <cuda_fp16.h>
#include <math.h>
#include <stdint.h>

#define Bn 8
#define Cc 128
#define Aa 16
#define Nn 4096

// log2(e) * (1/sqrt(16)) folded into Q so P = exp2(S)
#define QSCALE 0.3606737602222409f

// Scratch (no allocations allowed)
__device__ __align__(16) __half g_Qh[Bn * Nn * Aa];   // [b][n][16], prescaled
__device__ __align__(16) __half g_Kh[Bn * Nn * Aa];   // [b][n][16]
__device__ __align__(16) __half g_Vh[Bn * Cc * Nn];   // [b][c][n] channel-major

__device__ __forceinline__ uint32_t smem_u32(const void* p) {
    uint32_t a;
    asm("{ .reg .u64 t; cvta.to.shared.u64 t, %1; cvt.u32.u64 %0, t; }"
        : "=r"(a) : "l"(p));
    return a;
}
__device__ __forceinline__ float ex2f(float x) {
    float y; asm("ex2.approx.ftz.f32 %0, %1;" : "=f"(y) : "f"(x)); return y;
}
__device__ __forceinline__ uint32_t packh2(float hi, float lo) {
    uint32_t r;
    asm("cvt.rn.f16x2.f32 %0, %1, %2;" : "=r"(r) : "f"(hi), "f"(lo));
    return r;
}
__device__ __forceinline__ void cp16(uint32_t dst, const void* src) {
    asm volatile("cp.async.cg.shared.global [%0], [%1], 16;"
                 :: "r"(dst), "l"(src) : "memory");
}
#define CP_COMMIT() asm volatile("cp.async.commit_group;" ::: "memory")
#define CP_WAIT_ALL() asm volatile("cp.async.wait_group 0;" ::: "memory")

#define LDSM4(r, addr)                                                        \
    asm volatile("ldmatrix.sync.aligned.m8n8.x4.shared.b16 {%0,%1,%2,%3}, [%4];" \
                 : "=r"((r)[0]), "=r"((r)[1]), "=r"((r)[2]), "=r"((r)[3])     \
                 : "r"(addr))

__device__ __forceinline__ void mma_f16(float* d, const uint32_t* a,
                                        uint32_t b0, uint32_t b1) {
    asm volatile(
        "mma.sync.aligned.m16n8k16.row.col.f32.f16.f16.f32 "
        "{%0,%1,%2,%3}, {%4,%5,%6,%7}, {%8,%9}, {%0,%1,%2,%3};"
        : "+f"(d[0]), "+f"(d[1]), "+f"(d[2]), "+f"(d[3])
        : "r"(a[0]), "r"(a[1]), "r"(a[2]), "r"(a[3]), "r"(b0), "r"(b1));
}

// ---------------------------------------------------------------------------
// Q/K projection -> fp16 [b][n][16]; Q pre-scaled by 0.25*log2(e)
// ---------------------------------------------------------------------------
__global__ __launch_bounds__(256) void proj_qk_kernel(
    const float* __restrict__ x,
    const float* __restrict__ Wq, const float* __restrict__ bq,
    const float* __restrict__ Wk, const float* __restrict__ bk)
{
    __shared__ float Wqs[Aa * Cc];
    __shared__ float Wks[Aa * Cc];
    __shared__ float U[4224];          // union: Xs[2][16][128] / Part[128][33]

    int b   = blockIdx.y;
    int n0  = blockIdx.x * 128;
    int tid = threadIdx.x;
    int h   = tid >> 7;                // c-half: 0 -> c 0..63, 1 -> c 64..127
    int px  = tid & 127;

    for (int i = tid; i < Aa * Cc; i += 256) { Wqs[i] = Wq[i]; Wks[i] = Wk[i]; }

    float qa[Aa], ka[Aa];
#pragma unroll
    for (int a = 0; a < Aa; a++) { qa[a] = 0.f; ka[a] = 0.f; }

    const float* xb = x + (size_t)b * Cc * Nn + n0;
    float* Xs = U;                     // [2][16][128]

    for (int t = 0; t < 4; t++) {
        int cg = h * 64 + t * 16;
        __syncthreads();
#pragma unroll
        for (int cc = 0; cc < 16; cc++)
            Xs[h * 2048 + cc * 128 + px] = xb[(size_t)(cg + cc) * Nn + px];
        __syncthreads();
#pragma unroll 4
        for (int cc = 0; cc < 16; cc++) {
            float xv = Xs[h * 2048 + cc * 128 + px];
            int c = cg + cc;
#pragma unroll
            for (int a = 0; a < Aa; a++) {
                qa[a] += Wqs[a * Cc + c] * xv;
                ka[a] += Wks[a * Cc + c] * xv;
            }
        }
    }

    __syncthreads();                   // Xs reads done; reuse U as Part
    float* Part = U;                   // [128][33]
    if (h == 1) {
#pragma unroll
        for (int a = 0; a < Aa; a++) {
            Part[px * 33 + a]      = qa[a];
            Part[px * 33 + 16 + a] = ka[a];
        }
    }
    __syncthreads();
    if (h == 0) {
#pragma unroll
        for (int a = 0; a < Aa; a++) {
            qa[a] += Part[px * 33 + a];
            ka[a] += Part[px * 33 + 16 + a];
        }
        int n = n0 + px;
        __half2* qo = (__half2*)(g_Qh + ((size_t)b * Nn + n) * Aa);
        __half2* ko = (__half2*)(g_Kh + ((size_t)b * Nn + n) * Aa);
#pragma unroll
        for (int a2 = 0; a2 < 8; a2++) {
            float q0v = (qa[2 * a2]     + bq[2 * a2])     * QSCALE;
            float q1v = (qa[2 * a2 + 1] + bq[2 * a2 + 1]) * QSCALE;
            qo[a2] = __floats2half2_rn(q0v, q1v);
            ko[a2] = __floats2half2_rn(ka[2 * a2] + bk[2 * a2],
                                       ka[2 * a2 + 1] + bk[2 * a2 + 1]);
        }
    }
}

// ---------------------------------------------------------------------------
// V projection -> fp16 [b][c][n] (channel-major). Tile 32c x 256n, 128 thr.
// ---------------------------------------------------------------------------
__global__ __launch_bounds__(128) void proj_v_kernel(
    const float* __restrict__ x,
    const float* __restrict__ Wv, const float* __restrict__ bv)
{
    __shared__ float Wvs[32][33];
    __shared__ float Xs[32][256];

    int b    = blockIdx.z;
    int c0   = blockIdx.y * 32;
    int n0   = blockIdx.x * 256;
    int tid  = threadIdx.x;
    int lane = tid & 31;
    int wg   = tid >> 5;

    float acc[8][8];
#pragma unroll
    for (int ci = 0; ci < 8; ci++)
#pragma unroll
        for (int j = 0; j < 8; j++) acc[ci][j] = 0.f;

    for (int k0 = 0; k0 < Cc; k0 += 32) {
        __syncthreads();
#pragma unroll
        for (int i = 0; i < 8; i++) {
            int idx = tid + i * 128;
            int kk = idx >> 5, cc = idx & 31;
            Wvs[kk][cc] = Wv[(size_t)(c0 + cc) * Cc + k0 + kk];
        }
#pragma unroll
        for (int i = 0; i < 64; i++) {
            int idx = tid + i * 128;
            int kk = idx >> 8, nn = idx & 255;
            Xs[kk][nn] = x[((size_t)b * Cc + k0 + kk) * Nn + n0 + nn];
        }
        __syncthreads();
#pragma unroll 4
        for (int kk = 0; kk < 32; kk++) {
            float xv[8];
#pragma unroll
            for (int j = 0; j < 8; j++) xv[j] = Xs[kk][lane + j * 32];
#pragma unroll
            for (int ci = 0; ci < 8; ci++) {
                float w = Wvs[kk][wg * 8 + ci];
#pragma unroll
                for (int j = 0; j < 8; j++) acc[ci][j] += w * xv[j];
            }
        }
    }

#pragma unroll
    for (int ci = 0; ci < 8; ci++) {
        int c = c0 + wg * 8 + ci;
        float bias = bv[c];
        __half* vo = g_Vh + ((size_t)b * Cc + c) * Nn + n0;
#pragma unroll
        for (int j = 0; j < 8; j++)
            vo[lane + j * 32] = __float2half_rn(acc[ci][j] + bias);
    }
}

// ---------------------------------------------------------------------------
// Flash attention via mma.sync, r=2 register blocking on queries.
// CTA: 256 queries, 8 warps (256 thr). Warp wid owns q rows [wid*32, wid*32+32)
// as two m16 tiles; V fragments reused by both m-tiles (half LDSM per MMA).
// grid (16, 8) = 128 CTAs -> single wave on 148 SMs.
// ---------------------------------------------------------------------------
#define KT 64
#define NITER (Nn / KT)
#define K_BYTES (64 * 48)               // 3072
#define V_BYTES (128 * 144)             // 18432
#define BUF_BYTES (K_BYTES + V_BYTES)   // 21504
#define STAGE_BYTES (256 * 133 * 4)     // 136192
#define ATTN_SMEM STAGE_BYTES

__global__ __launch_bounds__(256, 1) void attn_kernel(float* __restrict__ out)
{
    extern __shared__ char smem[];
    const uint32_t sb = smem_u32(smem);
    const int tid  = threadIdx.x;
    const int wid  = tid >> 5;
    const int lane = tid & 31;
    const int lr   = lane & 7, lg = lane >> 3;   // ldmatrix row / group
    const int b    = blockIdx.y;
    const int q0g  = blockIdx.x * 256;

    const __half* Kg = g_Kh + (size_t)b * Nn * Aa;
    const __half* Vg = g_Vh + (size_t)b * Cc * Nn;

    // Q fragments for 2 m-tiles (rows wid*32 + mt*16 + ...)
    const int qrow = lane >> 2, qcb = (lane & 3) * 4;
    uint32_t qa[2][4];
#pragma unroll
    for (int mt = 0; mt < 2; mt++) {
        const char* qp = (const char*)(g_Qh
            + ((size_t)b * Nn + q0g + wid * 32 + mt * 16) * Aa);
        qa[mt][0] = *(const uint32_t*)(qp + qrow * 32 + qcb);
        qa[mt][1] = *(const uint32_t*)(qp + (qrow + 8) * 32 + qcb);
        qa[mt][2] = *(const uint32_t*)(qp + qrow * 32 + qcb + 16);
        qa[mt][3] = *(const uint32_t*)(qp + (qrow + 8) * 32 + qcb + 16);
    }

    float o[2][16][4];
#pragma unroll
    for (int mt = 0; mt < 2; mt++)
#pragma unroll
        for (int t = 0; t < 16; t++)
#pragma unroll
            for (int j = 0; j < 4; j++) o[mt][t][j] = 0.f;
    float l0[2] = {0.f, 0.f}, l1[2] = {0.f, 0.f};

    auto fill = [&](int kt, int buf) {
        uint32_t kb = sb + buf * BUF_BYTES;
        uint32_t vb = kb + K_BYTES;
        if (tid < 128) {   // K: 64 keys x 2 16B chunks = 128 cp
            int key = tid >> 1, h = tid & 1;
            cp16(kb + key * 48 + h * 16,
                 (const char*)Kg + ((size_t)(kt * KT + key) * Aa + h * 8) * 2);
        }
#pragma unroll
        for (int i = 0; i < 4; i++) {   // V: 128ch x 8 16B segs = 1024 cp
            int idx = tid + i * 256;
            int c = idx >> 3, seg = idx & 7;
            cp16(vb + c * 144 + seg * 16,
                 (const char*)Vg + ((size_t)c * Nn + kt * KT + seg * 8) * 2);
        }
        CP_COMMIT();
    };

    fill(0, 0);

    for (int kt = 0; kt < NITER; kt++) {
        CP_WAIT_ALL();
        __syncthreads();
        if (kt + 1 < NITER) fill(kt + 1, (kt + 1) & 1);

        uint32_t kb = sb + (kt & 1) * BUF_BYTES;
        uint32_t vb = kb + K_BYTES;

        // K fragments for 64 keys, loaded once, reused by both m-tiles
        uint32_t kf[4][4];
#pragma unroll
        for (int nt2 = 0; nt2 < 4; nt2++) {
            uint32_t addr = kb + (uint32_t)(nt2 * 16 + lr + (lg & 2) * 4) * 48
                               + (uint32_t)(lg & 1) * 16;
            LDSM4(kf[nt2], addr);
        }

        // S = Q K^T per m-tile; P = exp2(S) packed to fp16 A fragments
        uint32_t amt[2][4][4];
#pragma unroll
        for (int mt = 0; mt < 2; mt++) {
            float s[8][4];
#pragma unroll
            for (int i = 0; i < 8; i++)
#pragma unroll
                for (int j = 0; j < 4; j++) s[i][j] = 0.f;
#pragma unroll
            for (int nt2 = 0; nt2 < 4; nt2++) {
                mma_f16(s[2 * nt2],     qa[mt], kf[nt2][0], kf[nt2][1]);
                mma_f16(s[2 * nt2 + 1], qa[mt], kf[nt2][2], kf[nt2][3]);
            }
#pragma unroll
            for (int i = 0; i < 8; i++) {
                s[i][0] = ex2f(s[i][0]);
                s[i][1] = ex2f(s[i][1]);
                s[i][2] = ex2f(s[i][2]);
                s[i][3] = ex2f(s[i][3]);
                l0[mt] += s[i][0] + s[i][1];
                l1[mt] += s[i][2] + s[i][3];
            }
#pragma unroll
            for (int ks = 0; ks < 4; ks++) {
                amt[mt][ks][0] = packh2(s[2 * ks][1],     s[2 * ks][0]);
                amt[mt][ks][1] = packh2(s[2 * ks][3],     s[2 * ks][2]);
                amt[mt][ks][2] = packh2(s[2 * ks + 1][1], s[2 * ks + 1][0]);
                amt[mt][ks][3] = packh2(s[2 * ks + 1][3], s[2 * ks + 1][2]);
            }
        }

        // O += P V : all 128 channels; each V fragment reused by both m-tiles
#pragma unroll
        for (int ks = 0; ks < 4; ks++) {
#pragma unroll
            for (int t2 = 0; t2 < 8; t2++) {
                uint32_t bv[4];
                uint32_t addr = vb + (uint32_t)(t2 * 16 + lr + (lg & 2) * 4) * 144
                                   + (uint32_t)(ks * 32) + (uint32_t)(lg & 1) * 16;
                LDSM4(bv, addr);
                mma_f16(o[0][2 * t2],     amt[0][ks], bv[0], bv[1]);
                mma_f16(o[0][2 * t2 + 1], amt[0][ks], bv[2], bv[3]);
                mma_f16(o[1][2 * t2],     amt[1][ks], bv[0], bv[1]);
                mma_f16(o[1][2 * t2 + 1], amt[1][ks], bv[2], bv[3]);
            }
        }
    }

    // row sums (lanes sharing a row differ in bits 0..1)
    float inv0[2], inv1[2];
#pragma unroll
    for (int mt = 0; mt < 2; mt++) {
        l0[mt] += __shfl_xor_sync(0xffffffffu, l0[mt], 1);
        l0[mt] += __shfl_xor_sync(0xffffffffu, l0[mt], 2);
        l1[mt] += __shfl_xor_sync(0xffffffffu, l1[mt], 1);
        l1[mt] += __shfl_xor_sync(0xffffffffu, l1[mt], 2);
        inv0[mt] = 1.f / l0[mt];
        inv1[mt] = 1.f / l1[mt];
    }

    __syncthreads();   // done with tile buffers; reuse smem as stage [256][133]
    float* stage = (float*)smem;
    const int cb = (lane & 3) * 2;
#pragma unroll
    for (int mt = 0; mt < 2; mt++) {
        int r0 = wid * 32 + mt * 16 + qrow;
#pragma unroll
        for (int t = 0; t < 16; t++) {
            int ch = t * 8 + cb;
            stage[r0 * 133 + ch]           = o[mt][t][0] * inv0[mt];
            stage[r0 * 133 + ch + 1]       = o[mt][t][1] * inv0[mt];
            stage[(r0 + 8) * 133 + ch]     = o[mt][t][2] * inv1[mt];
            stage[(r0 + 8) * 133 + ch + 1] = o[mt][t][3] * inv1[mt];
        }
    }
    __syncthreads();

    // coalesced write: 128 ch x 256 n; stride 133 -> bank-conflict-free reads
#pragma unroll 8
    for (int ch = 0; ch < Cc; ch++) {
        out[((size_t)b * Cc + ch) * Nn + q0g + tid] = stage[tid * 133 + ch];
    }
}

// ---------------------------------------------------------------------------
extern "C" void kernel_launch(void* const* d_in, const int* in_sizes, int n_in,
                              void* d_out, int out_size)
{
    const float* x  = (const float*)d_in[0];
    const float* Wq = (const float*)d_in[1];
    const float* bq = (const float*)d_in[2];
    const float* Wk = (const float*)d_in[3];
    const float* bk = (const float*)d_in[4];
    const float* Wv = (const float*)d_in[5];
    const float* bv = (const float*)d_in[6];
    float* out = (float*)d_out;

    proj_qk_kernel<<<dim3(Nn / 128, Bn), 256>>>(x, Wq, bq, Wk, bk);
    proj_v_kernel<<<dim3(Nn / 256, Cc / 32, Bn), 128>>>(x, Wv, bv);

    cudaFuncSetAttribute(attn_kernel,
                         cudaFuncAttributeMaxDynamicSharedMemorySize,
                         ATTN_SMEM);
    attn_kernel<<<dim3(Nn / 256, Bn), 256, ATTN_SMEM>>>(out);
}